// round 1
// baseline (speedup 1.0000x reference)
#include <cuda_runtime.h>
#include <math.h>

// Problem constants
#define T_DIM   36
#define NPOLES  40
#define KDIM    160          // 4*N_POLES
#define PDIM    4096
#define BDIM    2
#define PCOLS   64           // columns per CTA
#define NCTA    128          // 8192 columns / 64
#define NTHREADS 160
#define MAXIT   100
#define LAM_C   0.1f
#define TOL_C   1e-4f

// ---------------- device globals (no allocation allowed) ----------------
__device__ float    g_Dmat[T_DIM * KDIM];   // normalized dictionary, [t][k]
__device__ float    g_A[KDIM * KDIM];       // I - DtD/L (symmetric)
__device__ float    g_lambd;
__device__ float    g_linv;
__device__ float    g_tts[MAXIT];
__device__ float    g_part[NCTA];           // per-CTA ||dx||^2 partials
__device__ unsigned g_count;                // grid barrier counter
__device__ unsigned g_gen;                  // grid barrier generation

// ---------------- setup: dictionary, DtD, L, A, tts, barrier reset ------
__global__ void setup_kernel(const float* __restrict__ Drr,
                             const float* __restrict__ Dtheta) {
    __shared__ float rbuf[256];
    __shared__ float s_linv;
    const int tid = threadIdx.x;

    // 1. Build normalized dictionary columns (one thread per column)
    if (tid < KDIM) {
        const int j = tid;
        const int g = j / NPOLES;    // 0: rr^i cos, 1: (-rr)^i cos, 2: rr^i sin, 3: (-rr)^i sin
        const int n = j % NPOLES;
        const float rr = Drr[n];
        const float th = Dtheta[n];
        float vals[T_DIM];
        float pr = 1.0f;
        float n2 = 0.0f;
        for (int i = 0; i < T_DIM; ++i) {
            float ang  = (float)i * th;
            float base = (g < 2) ? cosf(ang) : sinf(ang);
            float v = pr * base;
            if ((g & 1) && (i & 1)) v = -v;   // (-1)^i factor
            vals[i] = v;
            n2 += v * v;
            pr *= rr;
        }
        float G  = (n2 == 0.0f) ? 6.0f : sqrtf(n2);  // sqrt(T)=6 fallback
        float gi = 1.0f / G;
        for (int i = 0; i < T_DIM; ++i) g_Dmat[i * KDIM + j] = vals[i] * gi;
    }
    __syncthreads();

    // 2. DtD (stored temporarily in g_A) + Frobenius norm
    float sq = 0.0f;
    for (int e = tid; e < KDIM * KDIM; e += 256) {
        int i = e / KDIM, jj = e % KDIM;
        float s = 0.0f;
        for (int t = 0; t < T_DIM; ++t)
            s += g_Dmat[t * KDIM + i] * g_Dmat[t * KDIM + jj];
        g_A[e] = s;
        sq += s * s;
    }
    rbuf[tid] = sq;
    __syncthreads();
    if (tid == 0) {
        float tot = 0.0f;
        for (int i = 0; i < 256; ++i) tot += rbuf[i];
        float L = sqrtf(tot);
        s_linv  = 1.0f / L;
        g_linv  = s_linv;
        g_lambd = LAM_C * s_linv;
        // FISTA momentum coefficients (double, then cast — matches reference)
        double t = 1.0;
        for (int k = 0; k < MAXIT; ++k) {
            double tn = (1.0 + sqrt(1.0 + 4.0 * t * t)) * 0.5;
            g_tts[k] = (float)((t - 1.0) / tn);
            t = tn;
        }
        g_count = 0;
        g_gen   = 0;
    }
    __syncthreads();

    // 3. A = I - DtD * linv
    const float linv = s_linv;
    for (int e = tid; e < KDIM * KDIM; e += 256) {
        int i = e / KDIM, jj = e % KDIM;
        g_A[e] = ((i == jj) ? 1.0f : 0.0f) - g_A[e] * linv;
    }
    if (tid < NCTA) g_part[tid] = 0.0f;
}

// ---------------- persistent FISTA kernel ------------------------------
__global__ void __launch_bounds__(NTHREADS, 1)
fista_kernel(const float* __restrict__ x_in, float* __restrict__ out) {
    extern __shared__ float smem[];
    float* As = smem;                         // 160*160
    float* Ys = As + KDIM * KDIM;             // 160*64  (y; also stages D)
    float* Xs = Ys + KDIM * PCOLS;            // 160*64  (x_old; also stages x tile)
    float* Dt = Xs + KDIM * PCOLS;            // 160*64  (DtY * linv)
    __shared__ float red[NTHREADS];
    __shared__ int   s_stop;

    const int tid   = threadIdx.x;
    const int kr    = tid >> 3;               // 0..19  row group
    const int pc    = tid & 7;                // 0..7   col group
    const int kbase = kr * 8;
    const int pbase = pc * 8;
    const int cta   = blockIdx.x;
    const int b     = cta >> 6;               // batch (64 CTAs per batch)
    const int p0    = (cta & 63) * PCOLS;

    // Load A into shared
    for (int i = tid; i < KDIM * KDIM; i += NTHREADS) As[i] = g_A[i];
    // Stage x tile [36 x 64] into Xs (coalesced)
    for (int i = tid; i < T_DIM * PCOLS; i += NTHREADS) {
        int t = i >> 6, pp = i & 63;
        Xs[i] = x_in[(b * T_DIM + t) * PDIM + p0 + pp];
    }
    // Stage dictionary [36 x 160] into Ys
    for (int i = tid; i < T_DIM * KDIM; i += NTHREADS) Ys[i] = g_Dmat[i];
    __syncthreads();

    const float linv  = g_linv;
    const float lambd = g_lambd;

    // ---- DtY = linv * D^T x  -> Dt (8x8 register tile per thread) ----
    {
        float acc[64];
        #pragma unroll
        for (int i = 0; i < 64; ++i) acc[i] = 0.0f;
        #pragma unroll 2
        for (int t = 0; t < T_DIM; ++t) {
            float4 a0 = *(const float4*)(Ys + t * KDIM + kbase);
            float4 a1 = *(const float4*)(Ys + t * KDIM + kbase + 4);
            float4 y0 = *(const float4*)(Xs + t * PCOLS + pbase);
            float4 y1 = *(const float4*)(Xs + t * PCOLS + pbase + 4);
            float av[8] = {a0.x, a0.y, a0.z, a0.w, a1.x, a1.y, a1.z, a1.w};
            float yv[8] = {y0.x, y0.y, y0.z, y0.w, y1.x, y1.y, y1.z, y1.w};
            #pragma unroll
            for (int i = 0; i < 8; ++i)
                #pragma unroll
                for (int c = 0; c < 8; ++c)
                    acc[i * 8 + c] = fmaf(av[i], yv[c], acc[i * 8 + c]);
        }
        __syncthreads();
        #pragma unroll
        for (int i = 0; i < 8; ++i)
            #pragma unroll
            for (int c = 0; c < 8; ++c)
                Dt[(kbase + i) * PCOLS + pbase + c] = acc[i * 8 + c] * linv;
    }
    // x0 = 0, y0 = 0
    for (int i = tid; i < KDIM * PCOLS; i += NTHREADS) { Xs[i] = 0.0f; Ys[i] = 0.0f; }
    __syncthreads();

    // ---- main FISTA loop ----
    unsigned genl = 0;
    for (int it = 0; it < MAXIT; ++it) {
        float acc[64];
        #pragma unroll
        for (int i = 0; i < 64; ++i) acc[i] = 0.0f;

        // A @ y  (160-deep dot per output; 64 FFMA + 4 LDS.128 per j)
        #pragma unroll 2
        for (int j = 0; j < KDIM; ++j) {
            float4 a0 = *(const float4*)(As + j * KDIM + kbase);
            float4 a1 = *(const float4*)(As + j * KDIM + kbase + 4);
            float4 y0 = *(const float4*)(Ys + j * PCOLS + pbase);
            float4 y1 = *(const float4*)(Ys + j * PCOLS + pbase + 4);
            float av[8] = {a0.x, a0.y, a0.z, a0.w, a1.x, a1.y, a1.z, a1.w};
            float yv[8] = {y0.x, y0.y, y0.z, y0.w, y1.x, y1.y, y1.z, y1.w};
            #pragma unroll
            for (int i = 0; i < 8; ++i)
                #pragma unroll
                for (int c = 0; c < 8; ++c)
                    acc[i * 8 + c] = fmaf(av[i], yv[c], acc[i * 8 + c]);
        }

        const float tt = g_tts[it];
        float dsum = 0.0f;
        __syncthreads();   // all reads of Ys complete before overwrite

        // shrink + momentum + local ||dx||^2
        #pragma unroll
        for (int i = 0; i < 8; ++i) {
            #pragma unroll
            for (int c = 0; c < 8; ++c) {
                int idx = (kbase + i) * PCOLS + pbase + c;
                float v  = acc[i * 8 + c] + Dt[idx];
                float a  = fabsf(v) - lambd;
                float xn = (a > 0.0f) ? copysignf(a, v) : 0.0f;
                float xo = Xs[idx];
                float d  = xn - xo;
                dsum += d * d;
                Ys[idx] = xn * (1.0f + tt) - xo * tt;
                Xs[idx] = xn;
            }
        }

        // block-reduce dsum (fixed order -> deterministic)
        red[tid] = dsum;
        __syncthreads();
        if (tid == 0) {
            float s = 0.0f;
            for (int i = 0; i < NTHREADS; ++i) s += red[i];
            g_part[cta] = s;
        }

        // ---- software grid barrier ----
        __syncthreads();
        if (tid == 0) {
            __threadfence();
            unsigned tk = atomicAdd(&g_count, 1);
            if (tk == (unsigned)(gridDim.x - 1)) {
                g_count = 0;
                __threadfence();
                atomicAdd(&g_gen, 1);
            } else {
                while (*((volatile unsigned*)&g_gen) == genl) { __nanosleep(64); }
            }
            __threadfence();
        }
        __syncthreads();
        genl++;

        // global convergence decision (identical order in every CTA)
        if (tid < NCTA) red[tid] = *((volatile float*)(g_part + tid));
        __syncthreads();
        if (tid == 0) {
            float tot = 0.0f;
            for (int i = 0; i < NCTA; ++i) tot += red[i];
            float denom = (it == 0) ? (float)PDIM : (float)KDIM;
            s_stop = (sqrtf(tot) < TOL_C * denom) ? 1 : 0;
        }
        __syncthreads();
        if (s_stop) break;
    }

    // write output [B, 160, 4096]
    __syncthreads();
    for (int i = tid; i < KDIM * PCOLS; i += NTHREADS) {
        int k = i >> 6, pp = i & 63;
        out[(b * KDIM + k) * PDIM + p0 + pp] = Xs[i];
    }
}

// ---------------- launch ------------------------------------------------
extern "C" void kernel_launch(void* const* d_in, const int* in_sizes, int n_in,
                              void* d_out, int out_size) {
    const float* Drr    = (const float*)d_in[0];
    const float* Dtheta = (const float*)d_in[1];
    const float* x      = (const float*)d_in[2];
    float* out = (float*)d_out;

    const size_t smem = (size_t)(KDIM * KDIM + 3 * KDIM * PCOLS) * sizeof(float); // 225,280 B
    cudaFuncSetAttribute(fista_kernel, cudaFuncAttributeMaxDynamicSharedMemorySize, (int)smem);

    setup_kernel<<<1, 256>>>(Drr, Dtheta);
    fista_kernel<<<NCTA, NTHREADS, smem>>>(x, out);
}